// round 4
// baseline (speedup 1.0000x reference)
#include <cuda_runtime.h>

#define T_LEN 2048
#define BATCH 64
#define XDIM  64
#define HID   256
#define KH    256            // recurrent K (x part precomputed)
#define KQ    64             // K per quarter-warp

#define NCTA  128            // 2 batch-halves x 64 column-slices
#define NTHR  512            // 16 warps: (warp&3)=column, (warp>>2)=K-quarter

// Static device scratch (no cudaMalloc anywhere)
__device__ float4   g_xz[(size_t)T_LEN * HID * BATCH]; // [t][col][b] -> (i,f,g,o) pre-act
__device__ float    g_h[2][HID * BATCH];               // [buf][col*64 + b]
__device__ unsigned g_arr[NCTA];                       // per-CTA monotonic arrival slots

// ---------------- packed f32x2 helpers ----------------
__device__ __forceinline__ unsigned long long fma2_(unsigned long long a,
                                                    unsigned long long b,
                                                    unsigned long long c) {
    unsigned long long d;
    asm("fma.rn.f32x2 %0, %1, %2, %3;" : "=l"(d) : "l"(a), "l"(b), "l"(c));
    return d;
}
__device__ __forceinline__ unsigned long long add2_(unsigned long long a,
                                                    unsigned long long b) {
    unsigned long long d;
    asm("add.rn.f32x2 %0, %1, %2;" : "=l"(d) : "l"(a), "l"(b));
    return d;
}
__device__ __forceinline__ unsigned long long dup2_(float x) {
    unsigned long long d;
    asm("mov.b64 %0, {%1, %1};" : "=l"(d) : "r"(__float_as_uint(x)));
    return d;
}
__device__ __forceinline__ unsigned long long pack2_(float lo, float hi) {
    unsigned long long d;
    asm("mov.b64 %0, {%1, %2};" : "=l"(d) : "r"(__float_as_uint(lo)), "r"(__float_as_uint(hi)));
    return d;
}
__device__ __forceinline__ void unpack2_(unsigned long long v, float& lo, float& hi) {
    unsigned a, b;
    asm("mov.b64 {%0, %1}, %2;" : "=r"(a), "=r"(b) : "l"(v));
    lo = __uint_as_float(a); hi = __uint_as_float(b);
}
__device__ __forceinline__ float sigmoidf_(float x) {
    return 1.0f / (1.0f + __expf(-x));
}
__device__ __forceinline__ float tanh_fast_(float x) {   // 2*sigmoid(2x)-1
    return __fmaf_rn(2.0f, 1.0f / (1.0f + __expf(-2.0f * x)), -1.0f);
}

// ---------------------------------------------------------------------------
// Pre-kernel: g_xz[t][col][b] = bias + x[b,t,:] . w_ih[4 gate rows of col, :]
// ---------------------------------------------------------------------------
#define PG_COLS 32
__global__ void __launch_bounds__(256) xz_gemm_kernel(
    const float* __restrict__ x, const float* __restrict__ w_ih,
    const float* __restrict__ bias)
{
    extern __shared__ float ps[];
    float (*xs)[65] = (float(*)[65])ps;          // [b][k], padded
    float* ws = ps + 64 * 65;                    // [c][k][q]

    const int t       = blockIdx.y;
    const int colbase = blockIdx.x * PG_COLS;
    const int tid     = threadIdx.x;

    for (int i = tid; i < 64 * 16; i += 256) {
        int b = i >> 4, k4 = i & 15;
        float4 v = *(const float4*)(x + (size_t)b * (T_LEN * XDIM) + (size_t)t * XDIM + 4 * k4);
        xs[b][4 * k4 + 0] = v.x; xs[b][4 * k4 + 1] = v.y;
        xs[b][4 * k4 + 2] = v.z; xs[b][4 * k4 + 3] = v.w;
    }
    for (int i = tid; i < PG_COLS * 64 * 4; i += 256) {
        int q = i & 3, k = (i >> 2) & 63, c = i >> 8;
        ws[i] = w_ih[(q * HID + colbase + c) * XDIM + k];
    }
    __syncthreads();

    const int b  = tid & 63;
    const int cg = tid >> 6;
    unsigned long long acc01[8], acc23[8];
    #pragma unroll
    for (int c8 = 0; c8 < 8; ++c8) {
        int col = colbase + cg * 8 + c8;
        acc01[c8] = pack2_(bias[0 * HID + col], bias[1 * HID + col]);
        acc23[c8] = pack2_(bias[2 * HID + col], bias[3 * HID + col]);
    }
    #pragma unroll 4
    for (int k = 0; k < 64; ++k) {
        unsigned long long xv = dup2_(xs[b][k]);
        #pragma unroll
        for (int c8 = 0; c8 < 8; ++c8) {
            ulonglong2 w = *(ulonglong2*)&ws[((cg * 8 + c8) * 64 + k) * 4];
            acc01[c8] = fma2_(w.x, xv, acc01[c8]);
            acc23[c8] = fma2_(w.y, xv, acc23[c8]);
        }
    }
    #pragma unroll
    for (int c8 = 0; c8 < 8; ++c8) {
        int col = colbase + cg * 8 + c8;
        float4 o;
        unpack2_(acc01[c8], o.x, o.y);
        unpack2_(acc23[c8], o.z, o.w);
        g_xz[((size_t)t * HID + col) * BATCH + b] = o;
    }
}

// ---------------------------------------------------------------------------
// Barrier primitives: per-CTA monotonic slots, no atomics, no resets.
// ---------------------------------------------------------------------------
__device__ __forceinline__ void arrive_(int cta, unsigned val) {
    asm volatile("fence.acq_rel.gpu;" ::: "memory");     // drain this SM's stores
    asm volatile("st.relaxed.gpu.u32 [%0], %1;"
                 :: "l"(&g_arr[cta]), "r"(val) : "memory");
}
// Warp-cooperative wait: lane L checks slots 4L..4L+3 (coalesced acquire loads)
__device__ __forceinline__ void wait_all_(unsigned target, int lane) {
    const unsigned* p = g_arr + 4 * lane;
    bool ok;
    do {
        unsigned s0, s1, s2, s3;
        asm volatile("ld.acquire.gpu.u32 %0, [%1];" : "=r"(s0) : "l"(p + 0) : "memory");
        asm volatile("ld.acquire.gpu.u32 %0, [%1];" : "=r"(s1) : "l"(p + 1) : "memory");
        asm volatile("ld.acquire.gpu.u32 %0, [%1];" : "=r"(s2) : "l"(p + 2) : "memory");
        asm volatile("ld.acquire.gpu.u32 %0, [%1];" : "=r"(s3) : "l"(p + 3) : "memory");
        ok = ((int)(s0 - target) >= 0) & ((int)(s1 - target) >= 0) &
             ((int)(s2 - target) >= 0) & ((int)(s3 - target) >= 0);
    } while (!__all_sync(0xffffffffu, ok));
}

// ---------------------------------------------------------------------------
// Persistent LSTM. CTA (s,beta): cols [4s,4s+4), batches [32beta,32beta+32).
// warp w: col 4s+(w&3), K-quarter (w>>2) -> 4 warps per SMSP hide latency.
// ---------------------------------------------------------------------------
__global__ void __launch_bounds__(NTHR, 1) lstm_kernel(
    const float* __restrict__ w_hh, float* __restrict__ out)
{
    extern __shared__ __align__(16) float smem[];
    float* wsm = smem;                                   // [4c][256k][4g] 16KB
    float* hs  = smem + 4 * KH * 4;                      // [256k][32b]    32KB
    ulonglong2* part = (ulonglong2*)(hs + KH * 32);      // [3][4c][32l]    6KB

    const int tid   = threadIdx.x;
    const int warp  = tid >> 5;
    const int lane  = tid & 31;
    const int colw  = warp & 3;
    const int kq    = warp >> 2;          // 0..3
    const int cta   = blockIdx.x;
    const int s     = cta & 63;
    const int beta  = cta >> 6;
    const int col   = 4 * s + colw;
    const int b     = 32 * beta + lane;
    const bool owner = (kq == 0);

    unsigned base;                                        // own slot: race-free
    asm volatile("ld.relaxed.gpu.u32 %0, [%1];" : "=r"(base) : "l"(&g_arr[cta]));

    // Recurrent weights: wsm[((colw*256 + k)*4) + q], gate order i,f,g,o
    for (int idx = tid; idx < 4 * KH * 4; idx += NTHR) {
        int q  = idx & 3;
        int kk = (idx >> 2) & 255;
        int cw = idx >> 10;
        wsm[idx] = w_hh[(q * HID + 4 * s + cw) * HID + kk];
    }
    if (owner) g_h[0][col * BATCH + b] = 0.0f;            // h(0)=0
    float c_reg = 0.0f;
    float4 xz = make_float4(0.f, 0.f, 0.f, 0.f);
    if (owner) xz = __ldcg(&g_xz[(size_t)col * BATCH + b]);   // xz(t=0)

    __syncthreads();
    if (tid == 0) arrive_(cta, base + 1);                 // init barrier

    float4* hsv = (float4*)hs;
    const float* xb = hs + kq * KQ * 32 + lane;
    const ulonglong2* wr = (const ulonglong2*)wsm + (colw * KH + kq * KQ);
    const size_t out_base = (size_t)b * (T_LEN * HID) + col;
    unsigned tgt = base + 1;

    for (int t = 0; t < T_LEN; ++t) {
        if (warp == 0) wait_all_(tgt, lane);
        __syncthreads();

        // Stage h(t): 2048 float4 / 512 thr = 4 LDG.128 each (L2, L1-bypass)
        const float* hsrc = g_h[t & 1] + 32 * beta;
        #pragma unroll
        for (int i = 0; i < 4; ++i) {
            int idx = tid + i * NTHR;
            int k = idx >> 3, b4 = idx & 7;
            hsv[idx] = __ldcg((const float4*)(hsrc + k * BATCH + 4 * b4));
        }
        __syncthreads();

        // K-quarter GEMV: per k = LDS.32 + LDS.128 + dup + 2 FFMA2
        unsigned long long acc01 = 0ull, acc23 = 0ull;
        #pragma unroll 8
        for (int k = 0; k < KQ; ++k) {
            unsigned long long hv2 = dup2_(xb[k * 32]);
            ulonglong2 w = wr[k];
            acc01 = fma2_(w.x, hv2, acc01);
            acc23 = fma2_(w.y, hv2, acc23);
        }

        if (!owner) {
            ulonglong2 v; v.x = acc01; v.y = acc23;
            part[((kq - 1) * 4 + colw) * 32 + lane] = v;
        }
        asm volatile("bar.sync %0, 128;" :: "r"(1 + colw) : "memory");

        if (owner) {
            #pragma unroll
            for (int q = 0; q < 3; ++q) {
                ulonglong2 p = part[(q * 4 + colw) * 32 + lane];
                acc01 = add2_(acc01, p.x);
                acc23 = add2_(acc23, p.y);
            }
            acc01 = add2_(acc01, pack2_(xz.x, xz.y));     // + x-part + bias
            acc23 = add2_(acc23, pack2_(xz.z, xz.w));
            float a0, a1, a2, a3;
            unpack2_(acc01, a0, a1);
            unpack2_(acc23, a2, a3);

            const float ig = sigmoidf_(a0);
            const float fg = sigmoidf_(a1);
            const float gg = tanh_fast_(a2);
            const float og = sigmoidf_(a3);
            c_reg = fmaf(fg, c_reg, ig * gg);
            const float h = og * tanh_fast_(c_reg);

            g_h[(t & 1) ^ 1][col * BATCH + b] = h;
            out[out_base + (size_t)t * HID] = h;

            if (t + 1 < T_LEN)                            // hidden by barrier
                xz = __ldcg(&g_xz[((size_t)(t + 1) * HID + col) * BATCH + b]);
        }

        __syncthreads();                                  // all h stores issued
        tgt = base + 2 + (unsigned)t;
        if (tid == 0) arrive_(cta, tgt);
    }
}

// ---------------------------------------------------------------------------
extern "C" void kernel_launch(void* const* d_in, const int* in_sizes, int n_in,
                              void* d_out, int out_size) {
    (void)in_sizes; (void)n_in; (void)out_size;
    const float* x    = (const float*)d_in[0];
    const float* w_ih = (const float*)d_in[1];
    const float* w_hh = (const float*)d_in[2];
    const float* bias = (const float*)d_in[3];
    float* out = (float*)d_out;

    const int pg_smem = (64 * 65 + PG_COLS * 64 * 4) * (int)sizeof(float);
    cudaFuncSetAttribute(xz_gemm_kernel,
                         cudaFuncAttributeMaxDynamicSharedMemorySize, pg_smem);
    const int ls_smem = (4 * KH * 4 + KH * 32) * (int)sizeof(float)
                        + 3 * 4 * 32 * (int)sizeof(ulonglong2);   // 55296 B
    cudaFuncSetAttribute(lstm_kernel,
                         cudaFuncAttributeMaxDynamicSharedMemorySize, ls_smem);

    dim3 pg_grid(HID / PG_COLS, T_LEN);
    xz_gemm_kernel<<<pg_grid, 256, pg_smem>>>(x, w_ih, bias);
    lstm_kernel<<<NCTA, NTHR, ls_smem>>>(w_hh, out);
}

// round 5
// speedup vs baseline: 2.0886x; 2.0886x over previous
#include <cuda_runtime.h>

#define T_LEN 2048
#define BATCH 64
#define XDIM  64
#define HID   256
#define KH    256            // recurrent K (x part precomputed)
#define KQ    64             // K per quarter-warp

#define NCTA  128            // 2 batch-halves x 64 column-slices
#define NTHR  512            // 16 warps: (warp&3)=column, (warp>>2)=K-quarter

// Static device scratch (no cudaMalloc anywhere)
__device__ float4   g_xz[(size_t)T_LEN * HID * BATCH]; // [t][col][b] -> (i,f,g,o) pre-act
__device__ float    g_h[2][HID * BATCH];               // [buf][col*64 + b]
__device__ unsigned g_count;                           // barrier arrivals (self-reset)
__device__ unsigned g_phase;                           // monotonic phase

// ---------------- packed f32x2 helpers ----------------
__device__ __forceinline__ unsigned long long fma2_(unsigned long long a,
                                                    unsigned long long b,
                                                    unsigned long long c) {
    unsigned long long d;
    asm("fma.rn.f32x2 %0, %1, %2, %3;" : "=l"(d) : "l"(a), "l"(b), "l"(c));
    return d;
}
__device__ __forceinline__ unsigned long long add2_(unsigned long long a,
                                                    unsigned long long b) {
    unsigned long long d;
    asm("add.rn.f32x2 %0, %1, %2;" : "=l"(d) : "l"(a), "l"(b));
    return d;
}
__device__ __forceinline__ unsigned long long dup2_(float x) {
    unsigned long long d;
    asm("mov.b64 %0, {%1, %1};" : "=l"(d) : "r"(__float_as_uint(x)));
    return d;
}
__device__ __forceinline__ unsigned long long pack2_(float lo, float hi) {
    unsigned long long d;
    asm("mov.b64 %0, {%1, %2};" : "=l"(d) : "r"(__float_as_uint(lo)), "r"(__float_as_uint(hi)));
    return d;
}
__device__ __forceinline__ void unpack2_(unsigned long long v, float& lo, float& hi) {
    unsigned a, b;
    asm("mov.b64 {%0, %1}, %2;" : "=r"(a), "=r"(b) : "l"(v));
    lo = __uint_as_float(a); hi = __uint_as_float(b);
}
__device__ __forceinline__ float sigmoidf_(float x) {
    return 1.0f / (1.0f + __expf(-x));
}
__device__ __forceinline__ float tanh_fast_(float x) {   // 2*sigmoid(2x)-1
    return __fmaf_rn(2.0f, 1.0f / (1.0f + __expf(-2.0f * x)), -1.0f);
}

// ---------------------------------------------------------------------------
// Pre-kernel: g_xz[t][col][b] = bias + x[b,t,:] . w_ih[4 gate rows of col, :]
// ---------------------------------------------------------------------------
#define PG_COLS 32
__global__ void __launch_bounds__(256) xz_gemm_kernel(
    const float* __restrict__ x, const float* __restrict__ w_ih,
    const float* __restrict__ bias)
{
    extern __shared__ float ps[];
    float (*xs)[65] = (float(*)[65])ps;          // [b][k], padded
    float* ws = ps + 64 * 65;                    // [c][k][q]

    const int t       = blockIdx.y;
    const int colbase = blockIdx.x * PG_COLS;
    const int tid     = threadIdx.x;

    for (int i = tid; i < 64 * 16; i += 256) {
        int b = i >> 4, k4 = i & 15;
        float4 v = *(const float4*)(x + (size_t)b * (T_LEN * XDIM) + (size_t)t * XDIM + 4 * k4);
        xs[b][4 * k4 + 0] = v.x; xs[b][4 * k4 + 1] = v.y;
        xs[b][4 * k4 + 2] = v.z; xs[b][4 * k4 + 3] = v.w;
    }
    for (int i = tid; i < PG_COLS * 64 * 4; i += 256) {
        int q = i & 3, k = (i >> 2) & 63, c = i >> 8;
        ws[i] = w_ih[(q * HID + colbase + c) * XDIM + k];
    }
    __syncthreads();

    const int b  = tid & 63;
    const int cg = tid >> 6;
    unsigned long long acc01[8], acc23[8];
    #pragma unroll
    for (int c8 = 0; c8 < 8; ++c8) {
        int col = colbase + cg * 8 + c8;
        acc01[c8] = pack2_(bias[0 * HID + col], bias[1 * HID + col]);
        acc23[c8] = pack2_(bias[2 * HID + col], bias[3 * HID + col]);
    }
    #pragma unroll 4
    for (int k = 0; k < 64; ++k) {
        unsigned long long xv = dup2_(xs[b][k]);
        #pragma unroll
        for (int c8 = 0; c8 < 8; ++c8) {
            ulonglong2 w = *(ulonglong2*)&ws[((cg * 8 + c8) * 64 + k) * 4];
            acc01[c8] = fma2_(w.x, xv, acc01[c8]);
            acc23[c8] = fma2_(w.y, xv, acc23[c8]);
        }
    }
    #pragma unroll
    for (int c8 = 0; c8 < 8; ++c8) {
        int col = colbase + cg * 8 + c8;
        float4 o;
        unpack2_(acc01[c8], o.x, o.y);
        unpack2_(acc23[c8], o.z, o.w);
        g_xz[((size_t)t * HID + col) * BATCH + b] = o;
    }
}

// ---------------------------------------------------------------------------
// Barrier halves (R3-proven single-counter design, split across the loop edge)
// ---------------------------------------------------------------------------
__device__ __forceinline__ void bar_arrive_() {         // call by tid 0 only
    unsigned old;
    asm volatile("atom.acq_rel.gpu.add.u32 %0, [%1], 1;"
                 : "=r"(old) : "l"(&g_count) : "memory");
    if (old == (unsigned)(NCTA - 1)) {
        *(volatile unsigned*)&g_count = 0u;             // reset before release
        asm volatile("red.release.gpu.add.u32 [%0], 1;"
                     :: "l"(&g_phase) : "memory");
    }
}
__device__ __forceinline__ void bar_wait_(unsigned target) {  // tid 0 only
    unsigned p;
    do {
        asm volatile("ld.acquire.gpu.u32 %0, [%1];"
                     : "=r"(p) : "l"(&g_phase) : "memory");
    } while ((int)(p - target) < 0);
}

// ---------------------------------------------------------------------------
// Persistent LSTM. CTA (s,beta): cols [4s,4s+4), batches [32beta,32beta+32).
// warp w: col 4s+(w&3), K-quarter (w>>2) -> 4 warps/SMSP hide LDS/L2 latency.
// ---------------------------------------------------------------------------
__global__ void __launch_bounds__(NTHR, 1) lstm_kernel(
    const float* __restrict__ w_hh, float* __restrict__ out)
{
    extern __shared__ __align__(16) float smem[];
    float* wsm = smem;                                   // [4c][256k][4g] 16KB
    float* hs  = smem + 4 * KH * 4;                      // [256k][32b]    32KB
    ulonglong2* part = (ulonglong2*)(hs + KH * 32);      // [3][4c][32l]    6KB

    const int tid   = threadIdx.x;
    const int warp  = tid >> 5;
    const int lane  = tid & 31;
    const int colw  = warp & 3;
    const int kq    = warp >> 2;          // 0..3
    const int cta   = blockIdx.x;
    const int s     = cta & 63;
    const int beta  = cta >> 6;
    const int col   = 4 * s + colw;
    const int b     = 32 * beta + lane;
    const bool owner = (kq == 0);

    const unsigned p0 = *(volatile unsigned*)&g_phase;   // before any arrival!

    // Recurrent weights: wsm[((colw*256 + k)*4) + q], gate order i,f,g,o
    for (int idx = tid; idx < 4 * KH * 4; idx += NTHR) {
        int q  = idx & 3;
        int kk = (idx >> 2) & 255;
        int cw = idx >> 10;
        wsm[idx] = w_hh[(q * HID + 4 * s + cw) * HID + kk];
    }
    if (owner) g_h[0][col * BATCH + b] = 0.0f;           // h(0)=0
    float c_reg = 0.0f;
    float4 xz = make_float4(0.f, 0.f, 0.f, 0.f);
    if (owner) xz = __ldcg(&g_xz[(size_t)col * BATCH + b]);   // xz(t=0)

    __syncthreads();
    if (tid == 0) bar_arrive_();                          // init arrivals

    float4* hsv = (float4*)hs;
    const float* xb = hs + kq * KQ * 32 + lane;
    const ulonglong2* wr = (const ulonglong2*)wsm + (colw * KH + kq * KQ);
    const size_t out_base = (size_t)b * (T_LEN * HID) + col;

    for (int t = 0; t < T_LEN; ++t) {
        if (tid == 0) bar_wait_(p0 + 1 + (unsigned)t);
        __syncthreads();

        // Stage h(t): 2048 float4 / 512 thr = 4 LDG.128 each (L2, L1-bypass)
        const float* hsrc = g_h[t & 1] + 32 * beta;
        #pragma unroll
        for (int i = 0; i < 4; ++i) {
            int idx = tid + i * NTHR;
            int k = idx >> 3, b4 = idx & 7;
            hsv[idx] = __ldcg((const float4*)(hsrc + k * BATCH + 4 * b4));
        }
        __syncthreads();

        // K-quarter GEMV: per k = LDS.32 + LDS.128 + dup + 2 FFMA2
        unsigned long long acc01 = 0ull, acc23 = 0ull;
        #pragma unroll 8
        for (int k = 0; k < KQ; ++k) {
            unsigned long long hv2 = dup2_(xb[k * 32]);
            ulonglong2 w = wr[k];
            acc01 = fma2_(w.x, hv2, acc01);
            acc23 = fma2_(w.y, hv2, acc23);
        }

        if (!owner) {
            ulonglong2 v; v.x = acc01; v.y = acc23;
            part[((kq - 1) * 4 + colw) * 32 + lane] = v;
        }
        asm volatile("bar.sync %0, 128;" :: "r"(1 + colw) : "memory");

        if (owner) {
            #pragma unroll
            for (int q = 0; q < 3; ++q) {
                ulonglong2 p = part[(q * 4 + colw) * 32 + lane];
                acc01 = add2_(acc01, p.x);
                acc23 = add2_(acc23, p.y);
            }
            acc01 = add2_(acc01, pack2_(xz.x, xz.y));     // + x-part + bias
            acc23 = add2_(acc23, pack2_(xz.z, xz.w));
            float a0, a1, a2, a3;
            unpack2_(acc01, a0, a1);
            unpack2_(acc23, a2, a3);

            const float ig = sigmoidf_(a0);
            const float fg = sigmoidf_(a1);
            const float gg = tanh_fast_(a2);
            const float og = sigmoidf_(a3);
            c_reg = fmaf(fg, c_reg, ig * gg);
            const float h = og * tanh_fast_(c_reg);

            g_h[(t & 1) ^ 1][col * BATCH + b] = h;
            out[out_base + (size_t)t * HID] = h;

            if (t + 1 < T_LEN)                            // hidden by barrier
                xz = __ldcg(&g_xz[((size_t)(t + 1) * HID + col) * BATCH + b]);
        }

        __syncthreads();                                  // h stores done CTA-wide
        if (tid == 0) bar_arrive_();                      // fence via acq_rel atom
    }
}

// ---------------------------------------------------------------------------
extern "C" void kernel_launch(void* const* d_in, const int* in_sizes, int n_in,
                              void* d_out, int out_size) {
    (void)in_sizes; (void)n_in; (void)out_size;
    const float* x    = (const float*)d_in[0];
    const float* w_ih = (const float*)d_in[1];
    const float* w_hh = (const float*)d_in[2];
    const float* bias = (const float*)d_in[3];
    float* out = (float*)d_out;

    const int pg_smem = (64 * 65 + PG_COLS * 64 * 4) * (int)sizeof(float);
    cudaFuncSetAttribute(xz_gemm_kernel,
                         cudaFuncAttributeMaxDynamicSharedMemorySize, pg_smem);
    const int ls_smem = (4 * KH * 4 + KH * 32) * (int)sizeof(float)
                        + 3 * 4 * 32 * (int)sizeof(ulonglong2);   // 55296 B
    cudaFuncSetAttribute(lstm_kernel,
                         cudaFuncAttributeMaxDynamicSharedMemorySize, ls_smem);

    dim3 pg_grid(HID / PG_COLS, T_LEN);
    xz_gemm_kernel<<<pg_grid, 256, pg_smem>>>(x, w_ih, bias);
    lstm_kernel<<<NCTA, NTHR, ls_smem>>>(w_hh, out);
}

// round 6
// speedup vs baseline: 2.6559x; 1.2716x over previous
#include <cuda_runtime.h>

#define T_LEN 2048
#define BATCH 64
#define XDIM  64
#define HID   256
#define KH    256            // recurrent K (x part precomputed)
#define KQ    64             // K per quarter-warp

#define NCTA  128            // 2 batch-halves x 64 column-slices
#define NTHR  512            // 16 warps: (warp&3)=column, (warp>>2)=K-quarter

// Static device scratch (no cudaMalloc anywhere)
__device__ float4   g_xz[(size_t)T_LEN * HID * BATCH]; // [t][col][b] pre-activations
// Tagged h exchange buffer: float2 {h, tag} per value, viewed as float4 (2 batches)
__device__ __align__(16) float4 g_h2[2][KH][BATCH / 2];
__device__ unsigned g_epoch;                           // replay epoch counter

// ---------------- packed f32x2 helpers ----------------
__device__ __forceinline__ unsigned long long fma2_(unsigned long long a,
                                                    unsigned long long b,
                                                    unsigned long long c) {
    unsigned long long d;
    asm("fma.rn.f32x2 %0, %1, %2, %3;" : "=l"(d) : "l"(a), "l"(b), "l"(c));
    return d;
}
__device__ __forceinline__ unsigned long long add2_(unsigned long long a,
                                                    unsigned long long b) {
    unsigned long long d;
    asm("add.rn.f32x2 %0, %1, %2;" : "=l"(d) : "l"(a), "l"(b));
    return d;
}
__device__ __forceinline__ unsigned long long dup2_(float x) {
    unsigned long long d;
    asm("mov.b64 %0, {%1, %1};" : "=l"(d) : "r"(__float_as_uint(x)));
    return d;
}
__device__ __forceinline__ unsigned long long pack2_(float lo, float hi) {
    unsigned long long d;
    asm("mov.b64 %0, {%1, %2};" : "=l"(d) : "r"(__float_as_uint(lo)), "r"(__float_as_uint(hi)));
    return d;
}
__device__ __forceinline__ void unpack2_(unsigned long long v, float& lo, float& hi) {
    unsigned a, b;
    asm("mov.b64 {%0, %1}, %2;" : "=r"(a), "=r"(b) : "l"(v));
    lo = __uint_as_float(a); hi = __uint_as_float(b);
}
__device__ __forceinline__ float sigmoidf_(float x) {
    return 1.0f / (1.0f + __expf(-x));
}
__device__ __forceinline__ float tanh_fast_(float x) {   // 2*sigmoid(2x)-1
    return __fmaf_rn(2.0f, 1.0f / (1.0f + __expf(-2.0f * x)), -1.0f);
}

// Volatile 16B load (2 tagged h values); never hoisted/cached
__device__ __forceinline__ float4 vld4_(const float4* p) {
    float4 v;
    asm volatile("ld.volatile.global.v4.f32 {%0,%1,%2,%3}, [%4];"
                 : "=f"(v.x), "=f"(v.y), "=f"(v.z), "=f"(v.w) : "l"(p));
    return v;
}
// Publish one tagged h value (8B single transaction -> no tearing)
__device__ __forceinline__ void vst2_(float2* p, float h, unsigned tag) {
    asm volatile("st.volatile.global.v2.f32 [%0], {%1,%2};"
                 :: "l"(p), "f"(h), "f"(__uint_as_float(tag)) : "memory");
}

// ---------------------------------------------------------------------------
// Pre-kernel: g_xz[t][col][b] = bias + x[b,t,:] . w_ih[4 gate rows of col, :]
// ---------------------------------------------------------------------------
#define PG_COLS 32
__global__ void __launch_bounds__(256) xz_gemm_kernel(
    const float* __restrict__ x, const float* __restrict__ w_ih,
    const float* __restrict__ bias)
{
    extern __shared__ float ps[];
    float (*xs)[65] = (float(*)[65])ps;          // [b][k], padded
    float* ws = ps + 64 * 65;                    // [c][k][q]

    const int t       = blockIdx.y;
    const int colbase = blockIdx.x * PG_COLS;
    const int tid     = threadIdx.x;

    for (int i = tid; i < 64 * 16; i += 256) {
        int b = i >> 4, k4 = i & 15;
        float4 v = *(const float4*)(x + (size_t)b * (T_LEN * XDIM) + (size_t)t * XDIM + 4 * k4);
        xs[b][4 * k4 + 0] = v.x; xs[b][4 * k4 + 1] = v.y;
        xs[b][4 * k4 + 2] = v.z; xs[b][4 * k4 + 3] = v.w;
    }
    for (int i = tid; i < PG_COLS * 64 * 4; i += 256) {
        int q = i & 3, k = (i >> 2) & 63, c = i >> 8;
        ws[i] = w_ih[(q * HID + colbase + c) * XDIM + k];
    }
    __syncthreads();

    const int b  = tid & 63;
    const int cg = tid >> 6;
    unsigned long long acc01[8], acc23[8];
    #pragma unroll
    for (int c8 = 0; c8 < 8; ++c8) {
        int col = colbase + cg * 8 + c8;
        acc01[c8] = pack2_(bias[0 * HID + col], bias[1 * HID + col]);
        acc23[c8] = pack2_(bias[2 * HID + col], bias[3 * HID + col]);
    }
    #pragma unroll 4
    for (int k = 0; k < 64; ++k) {
        unsigned long long xv = dup2_(xs[b][k]);
        #pragma unroll
        for (int c8 = 0; c8 < 8; ++c8) {
            ulonglong2 w = *(ulonglong2*)&ws[((cg * 8 + c8) * 64 + k) * 4];
            acc01[c8] = fma2_(w.x, xv, acc01[c8]);
            acc23[c8] = fma2_(w.y, xv, acc23[c8]);
        }
    }
    #pragma unroll
    for (int c8 = 0; c8 < 8; ++c8) {
        int col = colbase + cg * 8 + c8;
        float4 o;
        unpack2_(acc01[c8], o.x, o.y);
        unpack2_(acc23[c8], o.z, o.w);
        g_xz[((size_t)t * HID + col) * BATCH + b] = o;
    }
}

// ---------------------------------------------------------------------------
// Persistent LSTM, barrier-free tagged dataflow.
// CTA (s,beta): cols [4s,4s+4), batches [32beta,32beta+32).
// warp w: col 4s+(w&3), K-quarter (w>>2). h values carry tag = epoch*2049+t+1;
// consumers spin on exactly the words they need. Depth-2 buffering makes WAR
// safe with no flags (publish(t+1) implies reads of slot t%2 are complete).
// ---------------------------------------------------------------------------
__global__ void __launch_bounds__(NTHR, 1) lstm_kernel(
    const float* __restrict__ w_hh, float* __restrict__ out)
{
    extern __shared__ __align__(16) float smem[];
    float* wsm = smem;                                   // [4c][256k][4g] 16KB
    float* hs  = smem + 4 * KH * 4;                      // [256k][32b]    32KB
    ulonglong2* part = (ulonglong2*)(hs + KH * 32);      // [3][4c][32l]    6KB
    __shared__ unsigned sh_epoch;

    const int tid   = threadIdx.x;
    const int warp  = tid >> 5;
    const int lane  = tid & 31;
    const int colw  = warp & 3;
    const int kq    = warp >> 2;          // 0..3
    const int cta   = blockIdx.x;
    const int s     = cta & 63;
    const int beta  = cta >> 6;
    const int col   = 4 * s + colw;
    const int b     = 32 * beta + lane;
    const bool owner = (kq == 0);

    if (tid == 0) sh_epoch = atomicAdd(&g_epoch, 1u) >> 7;   // /NCTA -> replay id

    // Recurrent weights: wsm[((colw*256 + k)*4) + q], gate order i,f,g,o
    for (int idx = tid; idx < 4 * KH * 4; idx += NTHR) {
        int q  = idx & 3;
        int kk = (idx >> 2) & 255;
        int cw = idx >> 10;
        wsm[idx] = w_hh[(q * HID + 4 * s + cw) * HID + kk];
    }
    __syncthreads();
    const unsigned epoch = sh_epoch;
    const unsigned tag0  = epoch * (unsigned)(T_LEN + 1) + 1u;  // tag of h(t) = tag0 + t

    float c_reg = 0.0f;
    float4 xz = make_float4(0.f, 0.f, 0.f, 0.f);
    float2* gh2 = (float2*)g_h2;
    if (owner) {
        vst2_(gh2 + ((size_t)0 * KH + col) * BATCH + b, 0.0f, tag0);  // h(0)=0
        xz = __ldcg(&g_xz[(size_t)col * BATCH + b]);                  // xz(t=0)
    }

    const float* xb = hs + kq * KQ * 32 + lane;
    const ulonglong2* wr = (const ulonglong2*)wsm + (colw * KH + kq * KQ);
    const size_t out_base = (size_t)b * (T_LEN * HID) + col;
    const float4* ghv_base = &g_h2[0][0][0];

    for (int t = 0; t < T_LEN; ++t) {
        const unsigned exp = tag0 + (unsigned)t;
        const float4* src = ghv_base + (size_t)(t & 1) * KH * (BATCH / 2);

        __syncthreads();   // all reads of hs/part from step t-1 complete

        // Stage h(t): 4096 float4 / 512 thr = 8 tagged loads each.
        // Phase 1: fire all 8 (MLP); Phase 2: re-spin only stale ones.
        float4 v[8];
        int kk_[8], bp_[8];
        #pragma unroll
        for (int i = 0; i < 8; ++i) {
            int idx = tid + i * NTHR;              // 0..4095
            kk_[i] = idx >> 4;                     // k
            bp_[i] = idx & 15;                     // batch-pair within half
            v[i] = vld4_(src + kk_[i] * (BATCH / 2) + 16 * beta + bp_[i]);
        }
        #pragma unroll
        for (int i = 0; i < 8; ++i) {
            while (__float_as_uint(v[i].y) != exp ||
                   __float_as_uint(v[i].w) != exp)
                v[i] = vld4_(src + kk_[i] * (BATCH / 2) + 16 * beta + bp_[i]);
            *(float2*)&hs[kk_[i] * 32 + 2 * bp_[i]] = make_float2(v[i].x, v[i].z);
        }
        __syncthreads();   // hs(t) fully staged

        // K-quarter GEMV: per k = LDS.32 + LDS.128 + dup + 2 FFMA2
        unsigned long long acc01 = 0ull, acc23 = 0ull;
        #pragma unroll 8
        for (int k = 0; k < KQ; ++k) {
            unsigned long long hv2 = dup2_(xb[k * 32]);
            ulonglong2 w = wr[k];
            acc01 = fma2_(w.x, hv2, acc01);
            acc23 = fma2_(w.y, hv2, acc23);
        }

        if (!owner) {
            ulonglong2 pv; pv.x = acc01; pv.y = acc23;
            part[((kq - 1) * 4 + colw) * 32 + lane] = pv;
        }
        asm volatile("bar.sync %0, 128;" :: "r"(1 + colw) : "memory");

        if (owner) {
            #pragma unroll
            for (int q = 0; q < 3; ++q) {
                ulonglong2 p = part[(q * 4 + colw) * 32 + lane];
                acc01 = add2_(acc01, p.x);
                acc23 = add2_(acc23, p.y);
            }
            acc01 = add2_(acc01, pack2_(xz.x, xz.y));     // + x-part + bias
            acc23 = add2_(acc23, pack2_(xz.z, xz.w));
            float a0, a1, a2, a3;
            unpack2_(acc01, a0, a1);
            unpack2_(acc23, a2, a3);

            const float ig = sigmoidf_(a0);
            const float fg = sigmoidf_(a1);
            const float gg = tanh_fast_(a2);
            const float og = sigmoidf_(a3);
            c_reg = fmaf(fg, c_reg, ig * gg);
            const float h = og * tanh_fast_(c_reg);

            // Publish FIRST (shortest path to consumers), then sideband stores
            vst2_(gh2 + ((size_t)((t + 1) & 1) * KH + col) * BATCH + b,
                  h, exp + 1u);
            out[out_base + (size_t)t * HID] = h;
            if (t + 1 < T_LEN)
                xz = __ldcg(&g_xz[((size_t)(t + 1) * HID + col) * BATCH + b]);
        }
        // no trailing barrier: next step's tag spins provide all ordering
    }
}

// ---------------------------------------------------------------------------
extern "C" void kernel_launch(void* const* d_in, const int* in_sizes, int n_in,
                              void* d_out, int out_size) {
    (void)in_sizes; (void)n_in; (void)out_size;
    const float* x    = (const float*)d_in[0];
    const float* w_ih = (const float*)d_in[1];
    const float* w_hh = (const float*)d_in[2];
    const float* bias = (const float*)d_in[3];
    float* out = (float*)d_out;

    const int pg_smem = (64 * 65 + PG_COLS * 64 * 4) * (int)sizeof(float);
    cudaFuncSetAttribute(xz_gemm_kernel,
                         cudaFuncAttributeMaxDynamicSharedMemorySize, pg_smem);
    const int ls_smem = (4 * KH * 4 + KH * 32) * (int)sizeof(float)
                        + 3 * 4 * 32 * (int)sizeof(ulonglong2);   // 55296 B
    cudaFuncSetAttribute(lstm_kernel,
                         cudaFuncAttributeMaxDynamicSharedMemorySize, ls_smem);

    dim3 pg_grid(HID / PG_COLS, T_LEN);
    xz_gemm_kernel<<<pg_grid, 256, pg_smem>>>(x, w_ih, bias);
    lstm_kernel<<<NCTA, NTHR, ls_smem>>>(w_hh, out);
}